// round 7
// baseline (speedup 1.0000x reference)
#include <cuda_runtime.h>
#include <cuda_fp16.h>
#include <math.h>
#include <stdint.h>

#define BATCH 4
#define CH    512
#define HWN   4096
#define NGROUPS 32
#define CPG   16

#define TM 128
#define TN 128
#define TK 32
#define STAGES 4

// ---------------- scratch (device globals; allocation-free) ----------------
__device__ __half g_h[(size_t)BATCH * CH * HWN];
__device__ __half g_qkv[3 * (size_t)BATCH * CH * HWN];   // q,k,v contiguous
__device__ __half g_o[(size_t)BATCH * CH * HWN];
__device__ __half g_s[(size_t)BATCH * HWN * HWN];        // unnormalized exp(S)
__device__ float  g_l[(size_t)BATCH * HWN];              // row sums
__device__ __half g_w[4 * CH * CH];                      // fp16 weights q,k,v,o
__device__ float  g_bias[3 * CH];                        // biases q,k,v

// ---------------- helpers ----------------
__device__ __forceinline__ uint32_t smem_u32(const void* p) {
    return (uint32_t)__cvta_generic_to_shared(p);
}
__device__ __forceinline__ void cp16(uint32_t dst, const void* src) {
    asm volatile("cp.async.cg.shared.global [%0], [%1], 16;\n" :: "r"(dst), "l"(src));
}
__device__ __forceinline__ void cp_commit() {
    asm volatile("cp.async.commit_group;\n");
}
template<int N> __device__ __forceinline__ void cp_wait() {
    asm volatile("cp.async.wait_group %0;\n" :: "n"(N));
}
__device__ __forceinline__ void ldmx4(uint32_t* r, uint32_t a) {
    asm volatile("ldmatrix.sync.aligned.m8n8.x4.shared.b16 {%0,%1,%2,%3}, [%4];"
        : "=r"(r[0]), "=r"(r[1]), "=r"(r[2]), "=r"(r[3]) : "r"(a));
}
__device__ __forceinline__ void ldmx4t(uint32_t* r, uint32_t a) {
    asm volatile("ldmatrix.sync.aligned.m8n8.x4.trans.shared.b16 {%0,%1,%2,%3}, [%4];"
        : "=r"(r[0]), "=r"(r[1]), "=r"(r[2]), "=r"(r[3]) : "r"(a));
}
__device__ __forceinline__ void mma_f16(float* d, const uint32_t* a, const uint32_t* b) {
    asm volatile(
        "mma.sync.aligned.m16n8k16.row.col.f32.f16.f16.f32 "
        "{%0,%1,%2,%3}, {%4,%5,%6,%7}, {%8,%9}, {%0,%1,%2,%3};"
        : "+f"(d[0]), "+f"(d[1]), "+f"(d[2]), "+f"(d[3])
        : "r"(a[0]), "r"(a[1]), "r"(a[2]), "r"(a[3]), "r"(b[0]), "r"(b[1]));
}

// ---------------- weight/bias staging ----------------
__global__ void cvt_w_kernel(const float* __restrict__ w0, const float* __restrict__ w1,
                             const float* __restrict__ w2, const float* __restrict__ w3,
                             const float* __restrict__ b0, const float* __restrict__ b1,
                             const float* __restrict__ b2,
                             __half* __restrict__ dst, float* __restrict__ bdst) {
    const int n = CH * CH;
    const float* srcs[4] = {w0, w1, w2, w3};
    for (int idx = blockIdx.x * blockDim.x + threadIdx.x; idx < 4 * n;
         idx += gridDim.x * blockDim.x)
        dst[idx] = __float2half(srcs[idx / n][idx % n]);
    if (blockIdx.x == 0) {
        const float* bs[3] = {b0, b1, b2};
        for (int idx = threadIdx.x; idx < 3 * CH; idx += blockDim.x)
            bdst[idx] = bs[idx / CH][idx % CH];
    }
}

// ---------------- GroupNorm (fp32 in, fp16 out) ----------------
__global__ void gn_kernel(const float* __restrict__ x,
                          const float* __restrict__ gamma,
                          const float* __restrict__ beta,
                          __half* __restrict__ h) {
    const int b = blockIdx.x / NGROUPS;
    const int g = blockIdx.x % NGROUPS;
    const int n = CPG * HWN;
    const float* xp = x + ((size_t)b * CH + (size_t)g * CPG) * HWN;
    __half*      hp = h + ((size_t)b * CH + (size_t)g * CPG) * HWN;

    float s = 0.f, ss = 0.f;
    for (int i = threadIdx.x; i < n; i += 256) {
        float v = xp[i];
        s += v; ss += v * v;
    }
    __shared__ float sh1[256], sh2[256];
    sh1[threadIdx.x] = s; sh2[threadIdx.x] = ss;
    __syncthreads();
    for (int o = 128; o > 0; o >>= 1) {
        if (threadIdx.x < o) {
            sh1[threadIdx.x] += sh1[threadIdx.x + o];
            sh2[threadIdx.x] += sh2[threadIdx.x + o];
        }
        __syncthreads();
    }
    const float mean = sh1[0] / (float)n;
    const float var  = sh2[0] / (float)n - mean * mean;
    const float inv  = rsqrtf(var + 1e-6f);

    for (int i = threadIdx.x; i < n; i += 256) {
        int c = g * CPG + i / HWN;
        hp[i] = __float2half((xp[i] - mean) * inv * gamma[c] + beta[c]);
    }
}

// ---------------- FP16 tensor-core GEMM, 4-stage cp.async + frag dbuf ------
// C[m,n] = op(A)*op(B); ATRANS: A stored [K,M]; BTRANS: B stored [N,K]
// EPI: 2 +bias+res (float out), 4 exp+rowsum (half out),
//      5 col-normalize (half out), 6 merged QKV: z=(proj,batch), +bias (half out)
template<bool ATRANS, bool BTRANS, int EPI>
__global__ __launch_bounds__(256)
void gemm_f16(const __half* __restrict__ Ag, const __half* __restrict__ Bg,
              void* __restrict__ Cg,
              const float* __restrict__ bias, const float* __restrict__ res,
              float* __restrict__ Lsum,
              int K, int lda, int ldb, int ldc,
              size_t strA, size_t strB, size_t strC, float scale)
{
    extern __shared__ __half smem[];
    constexpr int SA = ATRANS ? (TM + 8) : (TK + 8);
    constexpr int SB = BTRANS ? (TK + 8) : (TN + 8);
    constexpr int SZA = ATRANS ? TK * SA : TM * SA;
    constexpr int SZB = BTRANS ? TN * SB : TK * SB;
    constexpr int STG = SZA + SZB;
    constexpr bool HAS_BIAS = (EPI == 2 || EPI == 6);

    const int zz = blockIdx.z;
    const int proj = (EPI == 6) ? (zz >> 2) : 0;
    const int bz   = (EPI == 6) ? (zz & 3)  : zz;
    const int m0 = blockIdx.y * TM;
    const int n0 = blockIdx.x * TN;
    const __half* A = Ag + ((EPI == 6) ? (size_t)proj * CH * CH : (size_t)bz * strA);
    const __half* B = Bg + (size_t)bz * strB;
    const size_t coff = (EPI == 6) ? ((size_t)proj * BATCH + bz) * strC
                                   : (size_t)bz * strC;
    const float* R = (EPI == 2) ? (res + coff) : nullptr;
    const float* Bi = HAS_BIAS ? (bias + ((EPI == 6) ? proj * CH : 0)) : nullptr;
    float* L = (EPI == 4 || EPI == 5) ? (Lsum + (size_t)bz * HWN) : nullptr;

    const int tid  = threadIdx.x;
    const int wid  = tid >> 5;
    const int lane = tid & 31;
    const int gid  = lane >> 2;
    const int tig  = lane & 3;
    const int wm   = (wid >> 2) * 64;
    const int wn   = (wid & 3) * 32;
    const int lq   = lane >> 3;
    const int lr   = lane & 7;

    auto copy_tile = [&](int kt, int st) {
        __half* as = smem + st * STG;
        __half* bs = as + SZA;
        const int k0 = kt * TK;
        #pragma unroll
        for (int i = 0; i < 2; i++) {
            int idx = tid + i * 256;
            if (ATRANS) {
                int k = idx >> 4, c = idx & 15;
                cp16(smem_u32(as + k * SA + c * 8), A + (size_t)(k0 + k) * lda + m0 + c * 8);
            } else {
                int m = idx >> 2, c = idx & 3;
                cp16(smem_u32(as + m * SA + c * 8), A + (size_t)(m0 + m) * lda + k0 + c * 8);
            }
        }
        #pragma unroll
        for (int i = 0; i < 2; i++) {
            int idx = tid + i * 256;
            if (BTRANS) {
                int n = idx >> 2, c = idx & 3;
                cp16(smem_u32(bs + n * SB + c * 8), B + (size_t)(n0 + n) * ldb + k0 + c * 8);
            } else {
                int k = idx >> 4, c = idx & 15;
                cp16(smem_u32(bs + k * SB + c * 8), B + (size_t)(k0 + k) * ldb + n0 + c * 8);
            }
        }
    };

    auto load_a = [&](uint32_t* a, const __half* as, int kk) {
        #pragma unroll
        for (int i = 0; i < 4; i++) {
            const int mb = wm + i * 16;
            if (ATRANS) {
                ldmx4t(a + i * 4, smem_u32(as + (size_t)(kk + (lq >> 1) * 8 + lr) * SA
                                              + mb + (lq & 1) * 8));
            } else {
                ldmx4(a + i * 4, smem_u32(as + (size_t)(mb + lr + (lq & 1) * 8) * SA
                                             + kk + (lq >> 1) * 8));
            }
        }
    };
    auto load_b = [&](uint32_t* b, const __half* bs, int kk) {
        #pragma unroll
        for (int jj = 0; jj < 2; jj++) {
            const int nb = wn + jj * 16;
            if (BTRANS) {
                ldmx4(b + jj * 4, smem_u32(bs + (size_t)(nb + (lq >> 1) * 8 + lr) * SB
                                              + kk + (lq & 1) * 8));
            } else {
                ldmx4t(b + jj * 4, smem_u32(bs + (size_t)(kk + (lq & 1) * 8 + lr) * SB
                                               + nb + (lq >> 1) * 8));
            }
        }
    };

    float acc[4][4][4] = {};
    auto mma_all = [&](const uint32_t* a, const uint32_t* b) {
        #pragma unroll
        for (int i = 0; i < 4; i++)
            #pragma unroll
            for (int j = 0; j < 4; j++)
                mma_f16(acc[i][j], a + i * 4, b + (j >> 1) * 4 + (j & 1) * 2);
    };

    const int KT = K / TK;

    copy_tile(0, 0); cp_commit();
    copy_tile(1, 1); cp_commit();
    copy_tile(2, 2); cp_commit();
    cp_wait<2>();
    __syncthreads();

    uint32_t a0[16], b0[8], a1[16], b1[8];
    load_a(a0, smem, 0);
    load_b(b0, smem + SZA, 0);

    for (int kt = 0; kt < KT; kt++) {
        const __half* as = smem + (kt & 3) * STG;
        const __half* bs = as + SZA;

        // prefetch second half of this k-tile, then compute first half
        load_a(a1, as, 16);
        load_b(b1, bs, 16);
        mma_all(a0, b0);

        if (kt + 3 < KT) copy_tile(kt + 3, (kt + 3) & 3);
        cp_commit();
        cp_wait<2>();
        __syncthreads();

        // prefetch first half of next k-tile, then compute second half
        if (kt + 1 < KT) {
            const __half* as2 = smem + ((kt + 1) & 3) * STG;
            load_a(a0, as2, 0);
            load_b(b0, as2 + SZA, 0);
        }
        mma_all(a1, b1);
    }

    // ---- epilogue ----
    #pragma unroll
    for (int i = 0; i < 4; i++) {
        const int r0 = m0 + wm + i * 16 + gid;
        float b0v = 0.f, b1v = 0.f;
        if (HAS_BIAS) { b0v = Bi[r0]; b1v = Bi[r0 + 8]; }
        float rsum0 = 0.f, rsum1 = 0.f;
        #pragma unroll
        for (int j = 0; j < 4; j++) {
            const int c0 = n0 + wn + j * 8 + tig * 2;
            size_t i0 = (size_t)r0 * ldc + c0;
            size_t i1 = (size_t)(r0 + 8) * ldc + c0;
            float2 v0 = make_float2(acc[i][j][0], acc[i][j][1]);
            float2 v1 = make_float2(acc[i][j][2], acc[i][j][3]);
            if (HAS_BIAS) { v0.x += b0v; v0.y += b0v; v1.x += b1v; v1.y += b1v; }
            if (EPI == 2) {
                float2 r0v = *reinterpret_cast<const float2*>(&R[i0]);
                float2 r1v = *reinterpret_cast<const float2*>(&R[i1]);
                v0.x += r0v.x; v0.y += r0v.y; v1.x += r1v.x; v1.y += r1v.y;
            }
            if (EPI == 4) {
                v0.x = __expf(v0.x * scale); v0.y = __expf(v0.y * scale);
                v1.x = __expf(v1.x * scale); v1.y = __expf(v1.y * scale);
                rsum0 += v0.x + v0.y;
                rsum1 += v1.x + v1.y;
            }
            if (EPI == 5) {
                float l0 = L[c0], l1 = L[c0 + 1];
                v0.x /= l0; v0.y /= l1;
                v1.x /= l0; v1.y /= l1;
            }
            if (EPI == 2) {
                float* C = (float*)Cg + coff;
                *reinterpret_cast<float2*>(&C[i0]) = v0;
                *reinterpret_cast<float2*>(&C[i1]) = v1;
            } else {
                __half* C = (__half*)Cg + coff;
                *reinterpret_cast<__half2*>(&C[i0]) = __floats2half2_rn(v0.x, v0.y);
                *reinterpret_cast<__half2*>(&C[i1]) = __floats2half2_rn(v1.x, v1.y);
            }
        }
        if (EPI == 4) {
            rsum0 += __shfl_xor_sync(0xffffffffu, rsum0, 1);
            rsum0 += __shfl_xor_sync(0xffffffffu, rsum0, 2);
            rsum1 += __shfl_xor_sync(0xffffffffu, rsum1, 1);
            rsum1 += __shfl_xor_sync(0xffffffffu, rsum1, 2);
            if (tig == 0) {
                atomicAdd(&L[r0], rsum0);
                atomicAdd(&L[r0 + 8], rsum1);
            }
        }
    }
}

// ---------------- launch ----------------
extern "C" void kernel_launch(void* const* d_in, const int* in_sizes, int n_in,
                              void* d_out, int out_size) {
    const float* x        = (const float*)d_in[0];
    const float* gn_gamma = (const float*)d_in[1];
    const float* gn_beta  = (const float*)d_in[2];
    const float* wq       = (const float*)d_in[3];
    const float* bq       = (const float*)d_in[4];
    const float* wk       = (const float*)d_in[5];
    const float* bk       = (const float*)d_in[6];
    const float* wv       = (const float*)d_in[7];
    const float* bv       = (const float*)d_in[8];
    const float* wo       = (const float*)d_in[9];
    const float* bo       = (const float*)d_in[10];
    float* out = (float*)d_out;

    __half *ph, *pqkv, *po, *ps, *pw;
    float *pl, *pb;
    cudaGetSymbolAddress((void**)&ph, g_h);
    cudaGetSymbolAddress((void**)&pqkv, g_qkv);
    cudaGetSymbolAddress((void**)&po, g_o);
    cudaGetSymbolAddress((void**)&ps, g_s);
    cudaGetSymbolAddress((void**)&pl, g_l);
    cudaGetSymbolAddress((void**)&pw, g_w);
    cudaGetSymbolAddress((void**)&pb, g_bias);

    const size_t sCH = (size_t)CH * HWN;
    const size_t sSS = (size_t)HWN * HWN;
    const float scale = 0.04419417382415922f; // 512^-0.5
    const int WS = CH * CH;
    __half* pq = pqkv;
    __half* pk = pqkv + (size_t)BATCH * sCH;
    __half* pv = pqkv + 2 * (size_t)BATCH * sCH;

    const int smem_ff = STAGES * (TM * (TK + 8) + TK * (TN + 8)) * 2;
    const int smem_tf = STAGES * (TK * (TM + 8) + TK * (TN + 8)) * 2;
    const int smem_ft = STAGES * (TM * (TK + 8) + TN * (TK + 8)) * 2;

    cudaFuncSetAttribute(gemm_f16<false, false, 6>, cudaFuncAttributeMaxDynamicSharedMemorySize, smem_ff);
    cudaFuncSetAttribute(gemm_f16<false, false, 2>, cudaFuncAttributeMaxDynamicSharedMemorySize, smem_ff);
    cudaFuncSetAttribute(gemm_f16<true,  false, 4>, cudaFuncAttributeMaxDynamicSharedMemorySize, smem_tf);
    cudaFuncSetAttribute(gemm_f16<false, true,  5>, cudaFuncAttributeMaxDynamicSharedMemorySize, smem_ft);

    // 0) stage weights/biases; zero row sums
    cvt_w_kernel<<<256, 256>>>(wq, wk, wv, wo, bq, bk, bv, pw, pb);
    cudaMemsetAsync(pl, 0, (size_t)BATCH * HWN * sizeof(float));

    // 1) GroupNorm -> fp16 h
    gn_kernel<<<BATCH * NGROUPS, 256>>>(x, gn_gamma, gn_beta, ph);

    // 2) merged q,k,v projections: z = proj*4 + batch
    dim3 pg3(HWN / TN, CH / TM, 3 * BATCH);
    gemm_f16<false, false, 6><<<pg3, 256, smem_ff>>>(pw, ph, pqkv, pb, nullptr, nullptr,
        CH, CH, HWN, HWN, 0, sCH, sCH, 1.f);

    // 3) P~[n,m] = exp(scale * Q^T K), row sums -> g_l
    dim3 sg(HWN / TN, HWN / TM, BATCH);
    gemm_f16<true, false, 4><<<sg, 256, smem_tf>>>(pq, pk, ps, nullptr, nullptr, pl,
        CH, HWN, HWN, HWN, sCH, sCH, sSS, scale);

    // 4) O[c,n] = (sum_m V[c,m] P~[n,m]) / l[n]
    dim3 ag(HWN / TN, CH / TM, BATCH);
    gemm_f16<false, true, 5><<<ag, 256, smem_ft>>>(pv, ps, po, nullptr, nullptr, pl,
        HWN, HWN, HWN, HWN, sCH, sSS, sCH, 1.f);

    // 5) out projection + bias + residual (fp32 out)
    dim3 pg(HWN / TN, CH / TM, BATCH);
    gemm_f16<false, false, 2><<<pg, 256, smem_ff>>>(pw + 3 * WS, po, out, bo, x, nullptr,
        CH, CH, HWN, HWN, 0, sCH, sCH, 1.f);
}